// round 16
// baseline (speedup 1.0000x reference)
#include <cuda_runtime.h>
#include <math.h>
#include <float.h>
#include <limits.h>
#include <stdint.h>

#define BB 16
#define AA 8400
#define TT 128
#define CC 80
#define NN (BB*AA)
#define NG 4          // class groups in pass1
#define CG (CC/NG)    // classes per group (20)
#define NROWS (BB*TT)
#define CAP 128       // max stored ibc candidates per (b,t)
#define NGRP 263      // ceil(AA/32) anchor groups per image
#define NGRPH 132     // max groups per half

// ---------------- scratch (static device globals; no allocation) ----------------
// ALL state is either overwritten every launch or self-resetting (zero at launch
// entry; zero again at launch exit). CUDA zero-initializes these at module load,
// so the first launch sees the same state as every subsequent one.
__device__ float d_obj[NN];                     // obj logit (channel 4)
__device__ float d_A0[NN];                      // 1 + exp(-obj)
__device__ float2 d_SI[NN];                     // {S, in_box}
__device__ float d_apf[NN];                     // in_box ? area_p : -1e30
__device__ float4 d_pbox[NN];                   // pred boxes packed
__device__ float4 d_gbb[BB*NGRP];               // per-32-anchor-group bbox of in-box pred boxes
__device__ unsigned char d_inb[NN];             // in_box byte
__device__ unsigned char d_any4[(size_t)4*NN];  // per-chunk any flag
__device__ unsigned int d_ibc[BB*4*AA];         // in_box&in_center bitmask, word-major
__device__ float d_rowmax[NROWS];
__device__ int   d_mcnt[NN];                    // zero between launches
__device__ int   d_mt[NN];                      // holds max(TT - t); zero between launches
__device__ int   d_ccount[NROWS];               // zero between launches
__device__ int   d_clist[(size_t)NROWS*CAP];    // ibc candidate anchors per row
__device__ double d_acc[4];                     // zero between launches
__device__ unsigned int d_done;                 // zero between launches

__device__ __forceinline__ float bce(float x, float t) {
    return fmaxf(x, 0.f) - x * t + __logf(1.f + __expf(-fabsf(x)));
}
// jax.lax.top_k: stable — larger value first, ties -> smaller index first
__device__ __forceinline__ bool better(float k1, int i1, float k2, int i2) {
    return (k1 > k2) || (k1 == k2 && i1 < i2);
}

// D = logp - log1mp recomputed from A0 and class logit — one formula, all consumers
__device__ __forceinline__ float computeD(float A0, float x) {
    float u  = A0 * (1.f + __expf(-x));      // = 1/(so*sc)
    float p  = rsqrtf(u);
    float lp = fmaxf(-0.5f * __logf(u), -100.f);
    float l1 = fmaxf(__logf(1.f - p), -100.f);
    return lp - l1;
}

// register-resident indexed top-10 insert (static indexing, no spill)
__device__ __forceinline__ void insert10(float (&lk)[10], int (&li)[10], float k, int i) {
    if (!better(k, i, lk[9], li[9])) return;
    bool p[10];
    #pragma unroll
    for (int q = 0; q < 10; q++) p[q] = better(k, i, lk[q], li[q]);
    #pragma unroll
    for (int q = 9; q >= 1; q--) {
        if (p[q]) {
            lk[q] = p[q-1] ? lk[q-1] : k;
            li[q] = p[q-1] ? li[q-1] : i;
        }
    }
    if (p[0]) { lk[0] = k; li[0] = i; }
}

// branchless sorted top-10 VALUE network: 10 fmax + 10 fmin, no divergence
__device__ __forceinline__ void net10(float (&lk)[10], float v) {
    #pragma unroll
    for (int q = 0; q < 10; q++) {
        float hi = fmaxf(lk[q], v);
        v = fminf(lk[q], v);
        lk[q] = hi;
    }
}

// pair iou/cost for in-box anchors — identical math in row kernel and col conflict path
__device__ __forceinline__ void pair_iou_cost_inb(
    float4 pb, bool ibc, float S, float Dv,
    float x1, float y1, float x2, float y2, float area_t,
    float& iou_out, float& cost_out)
{
    float ltx = fmaxf(x1, pb.x), lty = fmaxf(y1, pb.y);
    float rbx = fminf(x2, pb.z), rby = fminf(y2, pb.w);
    float wx = fmaxf(rbx - ltx, 0.f), wy = fmaxf(rby - lty, 0.f);
    float inter = wx * wy;
    float area_p = fmaxf(pb.z - pb.x, 0.f) * fmaxf(pb.w - pb.y, 0.f);
    float iou = __fdividef(inter, area_t + area_p - inter + 1e-8f);
    float iouc = -__logf(iou + 1e-8f);
    float clsc = -(S + Dv);
    float cost = fmaf(3.0f, iouc, clsc);
    if (!ibc) cost += 100000.0f;
    iou_out = iou;
    cost_out = cost;
}

// ---------------- flags (runs FIRST): geometric flags + ibc candidate lists ----------------
__global__ void k_flags(const float* __restrict__ target,
                        const float* __restrict__ grid,
                        const float* __restrict__ str) {
    int b = blockIdx.z, ch = blockIdx.y;
    int a = blockIdx.x * blockDim.x + threadIdx.x;
    __shared__ float4 st4[32];
    __shared__ float2 sc2[32];
    if (threadIdx.x < 32) {
        const float* tb = target + ((size_t)b*TT + ch*32 + threadIdx.x)*6;
        float x1 = tb[2], y1 = tb[3], x2 = tb[4], y2 = tb[5];
        float4 v; v.x = x1; v.y = y1; v.z = x2; v.w = y2;
        st4[threadIdx.x] = v;
        float2 c; c.x = (x1 + x2) * 0.5f; c.y = (y1 + y2) * 0.5f;
        sc2[threadIdx.x] = c;
    }
    __syncthreads();
    if (a >= AA) return;
    float s = str[a];
    float xc = (grid[2*a] + 0.5f) * s;
    float yc = (grid[2*a+1] + 0.5f) * s;
    float r = 2.5f * s;
    unsigned w = 0;
    bool any = false;
    #pragma unroll 4
    for (int tt = 0; tt < 32; tt++) {
        float4 v = st4[tt];
        float2 c = sc2[tt];
        float dmin = fminf(fminf(xc - v.x, yc - v.y), fminf(v.z - xc, v.w - yc));
        bool ib = dmin > 0.f;
        bool ic = fmaxf(fabsf(xc - c.x), fabsf(yc - c.y)) < r;
        any |= (ib || ic);
        if (ib && ic) w |= (1u << tt);
    }
    d_ibc[(b*4 + ch)*AA + a] = w;
    d_any4[((size_t)ch*NN) + b*AA + a] = any ? 1 : 0;
    unsigned wb = w;
    while (wb) {
        int tt = __ffs(wb) - 1;
        wb &= wb - 1;
        int row = b*TT + ch*32 + tt;
        int p = atomicAdd(&d_ccount[row], 1);
        if (p < CAP) d_clist[(size_t)row*CAP + p] = a;
    }
}

// ---------------- pass1 (+combine fused): per-image blocks of 128 anchors ----------------
__global__ __launch_bounds__(512) void k_pass1(const float* __restrict__ pred) {
    __shared__ float tile[128*85];
    __shared__ float s_S[4][128];
    int b  = blockIdx.y;
    int a0 = blockIdx.x * 128;
    int cnt = min(128, AA - a0);
    const float* src = pred + ((size_t)b*AA + a0) * 85;
    for (int j = threadIdx.x; j < cnt*85; j += 512)
        tile[j] = src[j];
    __syncthreads();

    int al = threadIdx.x & 127;
    int g  = threadIdx.x >> 7;
    bool valid = al < cnt;
    int i  = b*AA + a0 + al;
    const float* row = tile + al*85;

    float S = 0.f;
    float4 pb = make_float4(0.f, 0.f, 0.f, 0.f);
    if (valid) {
        float xo = row[4];
        float A0 = 1.f + __expf(-xo);
        if (g == 0) {
            pb.x = row[0]; pb.y = row[1]; pb.z = row[2]; pb.w = row[3];
            d_pbox[i] = pb;
            d_obj[i] = xo;
            d_A0[i] = A0;
        }
        int c0 = g * CG;
        #pragma unroll 5
        for (int cc = 0; cc < CG; cc++) {
            float xc = row[5 + c0 + cc];
            float u  = A0 * (1.f + __expf(-xc));
            float p  = rsqrtf(u);
            float l1 = fmaxf(__logf(1.f - p), -100.f);
            S += l1;
        }
    }
    s_S[g][al] = S;
    __syncthreads();
    if (g != 0) return;

    // g==0 quarter-block (4 warps, warp w = image-local group a0/32 + w)
    bool inbv = false;
    if (valid) {
        float Ssum = s_S[0][al] + s_S[1][al] + s_S[2][al] + s_S[3][al];  // same order as before
        size_t ii = (size_t)i;
        unsigned char v = d_any4[ii] | d_any4[ii + (size_t)NN]
                        | d_any4[ii + (size_t)2*NN] | d_any4[ii + (size_t)3*NN];
        d_inb[i] = v;
        float2 si; si.x = Ssum; si.y = v ? 1.f : 0.f;
        d_SI[i] = si;
        float area_p = fmaxf(pb.z - pb.x, 0.f) * fmaxf(pb.w - pb.y, 0.f);
        d_apf[i] = v ? area_p : -1e30f;
        inbv = v != 0;
    }
    // warp bbox reduction over this image-local 32-anchor group
    float bx1 = inbv ? pb.x :  FLT_MAX;
    float by1 = inbv ? pb.y :  FLT_MAX;
    float bx2 = inbv ? pb.z : -FLT_MAX;
    float by2 = inbv ? pb.w : -FLT_MAX;
    #pragma unroll
    for (int o = 16; o; o >>= 1) {
        bx1 = fminf(bx1, __shfl_xor_sync(0xffffffffu, bx1, o));
        by1 = fminf(by1, __shfl_xor_sync(0xffffffffu, by1, o));
        bx2 = fmaxf(bx2, __shfl_xor_sync(0xffffffffu, bx2, o));
        by2 = fmaxf(by2, __shfl_xor_sync(0xffffffffu, by2, o));
    }
    if ((al & 31) == 0 && valid) {
        float4 gg; gg.x = bx1; gg.y = by1; gg.z = bx2; gg.w = by2;
        d_gbb[b*NGRP + ((a0 + al) >> 5)] = gg;
    }
}

// ---------------- warp merges (smem scratch) ----------------
__device__ __forceinline__ void warp_merge10(float* K, int* I, int lane) {
    for (int step = 1; step < 32; step <<= 1) {
        __syncwarp();
        if ((lane & (2*step - 1)) == 0) {
            int o = lane*10, p = (lane + step)*10;
            int pa = 0, pb = 0;
            float ov[10]; int oi[10];
            #pragma unroll
            for (int j = 0; j < 10; j++) {
                float ka = K[o + pa]; int ia = I[o + pa];
                float kb = K[p + pb]; int ib = I[p + pb];
                if (better(ka, ia, kb, ib)) { ov[j] = ka; oi[j] = ia; pa++; }
                else                        { ov[j] = kb; oi[j] = ib; pb++; }
            }
            #pragma unroll
            for (int j = 0; j < 10; j++) { K[o + j] = ov[j]; I[o + j] = oi[j]; }
        }
    }
    __syncwarp();
}

__device__ __forceinline__ void warp_merge10v(float* K, int lane) {
    for (int step = 1; step < 32; step <<= 1) {
        __syncwarp();
        if ((lane & (2*step - 1)) == 0) {
            int o = lane*10, p = (lane + step)*10;
            int pa = 0, pb = 0;
            float ov[10];
            #pragma unroll
            for (int j = 0; j < 10; j++) {
                float ka = K[o + pa];
                float kb = K[p + pb];
                if (ka >= kb) { ov[j] = ka; pa++; }
                else          { ov[j] = kb; pb++; }
            }
            #pragma unroll
            for (int j = 0; j < 10; j++) K[o + j] = ov[j];
        }
    }
    __syncwarp();
}

// ---------------- row pass: 4 rows x 2 warps, ballot compaction, dual-list ILP scan ----------------
__global__ __launch_bounds__(256) void k_row(const float* __restrict__ target,
                                             const float* __restrict__ pred) {
    __shared__ __align__(16) float4 s_gb[NGRP];   // group bboxes, staged once
    __shared__ float mKs[8*320];
    __shared__ int   mIs[8*320];
    __shared__ int   s_list[8][NGRPH];            // per-warp surviving group ids

    int b  = blockIdx.y;
    int tg = blockIdx.x;                     // 0..31 target groups of 4
    int warp = threadIdx.x >> 5, lane = threadIdx.x & 31;
    int t = tg*4 + (warp >> 1);
    int half = warp & 1;
    int row = b*TT + t;
    const float* tr = target + (size_t)row * 6;
    float x1 = tr[2], y1 = tr[3], x2 = tr[4], y2 = tr[5];
    int ci = (int)tr[1];
    float area_t = fmaxf(x2 - x1, 0.f) * fmaxf(y2 - y1, 0.f);
    float area_te = area_t + 1e-8f;
    unsigned tbit = 1u << (t & 31);
    int chunk = t >> 5;

    const float4* Pg = d_pbox + b*AA;
    const float*  Ag = d_apf + b*AA;
    const float2* Sg = d_SI + b*AA;
    const unsigned* Wg = d_ibc + (b*4 + chunk)*AA;

    // stage group bboxes once
    for (int g = threadIdx.x; g < NGRP; g += 256)
        s_gb[g] = d_gbb[b*NGRP + g];
    __syncthreads();

    // ---- ballot compaction: each lane tests a different group (5 rounds for 132) ----
    int nHalf = (NGRP - half + 1) >> 1;      // half=0: 132, half=1: 131
    int cntw = 0;
    #pragma unroll
    for (int r = 0; r < (NGRPH + 31)/32; r++) {
        int j = lane + r*32;
        int g = half + 2*j;
        bool surv = false;
        if (j < nHalf) {
            float4 gb = s_gb[g];
            surv = !(gb.x >= x2 || gb.z <= x1 || gb.y >= y2 || gb.w <= y1);
        }
        unsigned m = __ballot_sync(0xffffffffu, surv);
        if (surv) s_list[warp][cntw + __popc(m & ((1u << lane) - 1))] = g;
        cntw += __popc(m);
    }

    // ---- dual-list scan: 2 groups/iter into independent top-10 lists (2x ILP) ----
    float lkA[10], lkB[10];
    #pragma unroll
    for (int j = 0; j < 10; j++) { lkA[j] = 0.f; lkB[j] = 0.f; }   // iou of skipped/masked is 0

    int k = 0;
    for (; k + 1 < cntw; k += 2) {
        int g0 = s_list[warp][k], g1 = s_list[warp][k+1];
        int a0 = g0*32 + lane,    a1 = g1*32 + lane;
        bool v0 = a0 < AA, v1 = a1 < AA;
        float4 p0, p1; float q0, q1;
        if (v0) { p0 = Pg[a0]; q0 = Ag[a0]; }
        if (v1) { p1 = Pg[a1]; q1 = Ag[a1]; }
        if (v0) {
            float ltx = fmaxf(x1, p0.x), lty = fmaxf(y1, p0.y);
            float rbx = fminf(x2, p0.z), rby = fminf(y2, p0.w);
            float wx = fmaxf(rbx - ltx, 0.f), wy = fmaxf(rby - lty, 0.f);
            float inter = wx * wy;
            float iou = __fdividef(inter, (area_te + q0) - inter);
            net10(lkA, iou);
        }
        if (v1) {
            float ltx = fmaxf(x1, p1.x), lty = fmaxf(y1, p1.y);
            float rbx = fminf(x2, p1.z), rby = fminf(y2, p1.w);
            float wx = fmaxf(rbx - ltx, 0.f), wy = fmaxf(rby - lty, 0.f);
            float inter = wx * wy;
            float iou = __fdividef(inter, (area_te + q1) - inter);
            net10(lkB, iou);
        }
    }
    if (k < cntw) {
        int g0 = s_list[warp][k];
        int a0 = g0*32 + lane;
        if (a0 < AA) {
            float4 p0 = Pg[a0]; float q0 = Ag[a0];
            float ltx = fmaxf(x1, p0.x), lty = fmaxf(y1, p0.y);
            float rbx = fminf(x2, p0.z), rby = fminf(y2, p0.w);
            float wx = fmaxf(rbx - ltx, 0.f), wy = fmaxf(rby - lty, 0.f);
            float inter = wx * wy;
            float iou = __fdividef(inter, (area_te + q0) - inter);
            net10(lkA, iou);
        }
    }
    // merge: top-10 of union = insert B's top-10 into A (exact, stays sorted)
    #pragma unroll
    for (int j = 0; j < 10; j++) net10(lkA, lkB[j]);

    float* mK = mKs + warp*320;
    int*   mI = mIs + warp*320;

    // per-warp iou value merge
    #pragma unroll
    for (int j = 0; j < 10; j++) mK[lane*10 + j] = lkA[j];
    warp_merge10v(mK, lane);
    __syncthreads();   // partner lists visible

    if (half == 1) return;   // odd warps done

    // even-warp leader: merge partner's list, dyn_k, rowmax
    int dk = 0;
    if (lane == 0) {
        float* pK = mKs + (warp + 1)*320;
        float ov[10];
        int pa = 0, pb = 0;
        #pragma unroll
        for (int j = 0; j < 10; j++) {
            float ka = mK[pa], kb = pK[pb];
            if (ka >= kb) { ov[j] = ka; pa++; }
            else          { ov[j] = kb; pb++; }
        }
        float s = 0.f;
        #pragma unroll
        for (int j = 0; j < 10; j++) s += ov[j];
        dk = (int)s;                 // truncation, matches astype(int32)
        if (dk < 1) dk = 1; if (dk > 10) dk = 10;
        d_rowmax[row] = ov[0];
    }
    dk = __shfl_sync(0xffffffffu, dk, 0);
    __syncwarp();

    // ---- cost phase (even warp only): ibc candidate list ----
    float lkC[10]; int liC[10];
    #pragma unroll
    for (int j = 0; j < 10; j++) { lkC[j] = -FLT_MAX; liC[j] = INT_MAX; }
    int cnt = d_ccount[row];
    if (cnt >= 10 && cnt <= CAP) {
        const int* lst = d_clist + (size_t)row*CAP;
        for (int kk = lane; kk < cnt; kk += 32) {
            int a = lst[kk];
            float4 pb = Pg[a];
            float S = Sg[a].x;
            float Dv = computeD(d_A0[b*AA + a],
                                pred[((size_t)(b*AA + a))*85 + 5 + ci]);
            float iou, cost;
            pair_iou_cost_inb(pb, true, S, Dv, x1, y1, x2, y2, area_t, iou, cost);
            insert10(lkC, liC, -cost, a);
        }
    } else {
        // rare fallback: exact full-row scan (original semantics incl. penalties)
        for (int a = lane; a < AA; a += 32) {
            float4 pb = Pg[a];
            float2 si = Sg[a];
            bool inb = si.y != 0.f;
            bool ibc = (Wg[a] & tbit) != 0;
            float Dv = computeD(d_A0[b*AA + a],
                                pred[((size_t)(b*AA + a))*85 + 5 + ci]);
            float iou, cost;
            pair_iou_cost_inb(pb, ibc, si.x, Dv, x1, y1, x2, y2, area_t, iou, cost);
            if (!inb) cost += 1000000000.0f;
            insert10(lkC, liC, -cost, a);
        }
    }

    #pragma unroll
    for (int j = 0; j < 10; j++) { mK[lane*10 + j] = lkC[j]; mI[lane*10 + j] = liC[j]; }
    warp_merge10(mK, mI, lane);
    if (lane == 0) {
        for (int j = 0; j < dk; j++) {
            int aa = mI[j];
            if (aa == INT_MAX) break;
            if (d_inb[b*AA + aa]) {
                atomicAdd(&d_mcnt[b*AA + aa], 1);
                atomicMax(&d_mt[b*AA + aa], TT - t);   // max(TT-t) == min t; zero-init safe
            }
        }
        d_ccount[row] = 0;   // self-reset for next launch
    }
}

// ---------------- col pass (+finalize fused): iou-only piou + conflict argmin + loss ----------------
__global__ __launch_bounds__(256) void k_col(const float* __restrict__ pred,
                                             const float* __restrict__ target,
                                             float* __restrict__ out, int out_n) {
    int b = blockIdx.y;
    int a = blockIdx.x * blockDim.x + threadIdx.x;
    int tid = threadIdx.x;
    __shared__ float4 s_tb[TT];
    __shared__ float s_ar[TT], s_inv[TT];
    __shared__ int   s_ci[TT];
    if (tid < TT) {
        const float* tb = target + ((size_t)b*TT + tid)*6;
        float X1 = tb[2], Y1 = tb[3], X2 = tb[4], Y2 = tb[5];
        float4 v; v.x = X1; v.y = Y1; v.z = X2; v.w = Y2;
        s_tb[tid] = v;
        s_ar[tid] = fmaxf(X2 - X1, 0.f) * fmaxf(Y2 - Y1, 0.f);
        s_ci[tid] = (int)tb[1];
        s_inv[tid] = __fdividef(1.f, d_rowmax[b*TT + tid] + 1e-8f);
    }
    __syncthreads();

    float t_lbox = 0.f, t_m = 0.f, t_lobj = 0.f, t_lcls = 0.f;
    if (a < AA) {
        int ba = b*AA + a;
        float4 pb = d_pbox[ba];
        float2 si = d_SI[ba];
        bool inb = si.y != 0.f;
        float S = si.x;

        float piou = 0.f;
        if (inb) {
            float area_p = fmaxf(pb.z - pb.x, 0.f) * fmaxf(pb.w - pb.y, 0.f);
            #pragma unroll 8
            for (int t = 0; t < TT; t++) {
                float4 tb = s_tb[t];
                float ltx = fmaxf(tb.x, pb.x), lty = fmaxf(tb.y, pb.y);
                float rbx = fminf(tb.z, pb.z), rby = fminf(tb.w, pb.w);
                float wx = fmaxf(rbx - ltx, 0.f), wy = fmaxf(rby - lty, 0.f);
                float inter = wx * wy;
                float iou = __fdividef(inter, s_ar[t] + area_p - inter + 1e-8f);
                piou = fmaxf(piou, iou * s_inv[t]);
            }
        }
        float objt = inb ? fminf(fmaxf(piou, 0.f), 1.f) : 0.f;
        t_lobj = bce(d_obj[ba], objt);

        int cnt = d_mcnt[ba];
        int mtv = d_mt[ba];
        if (cnt != 0) { d_mcnt[ba] = 0; d_mt[ba] = 0; }   // self-reset for next launch
        int tp = -1;
        if (cnt == 1) tp = TT - mtv;
        else if (cnt > 1) {
            unsigned wv[4];
            #pragma unroll
            for (int ch = 0; ch < 4; ch++) wv[ch] = d_ibc[(b*4 + ch)*AA + a];
            const float* prow = pred + (size_t)ba * 85;
            float A0 = d_A0[ba];
            float bestc = FLT_MAX; int bestt = 0;
            for (int t = 0; t < TT; t++) {
                bool ibc = (wv[t >> 5] >> (t & 31)) & 1u;
                float4 tb = s_tb[t];
                float Dv = computeD(A0, prow[5 + s_ci[t]]);
                float iou, cost;
                pair_iou_cost_inb(pb, ibc, S, Dv,
                                  tb.x, tb.y, tb.z, tb.w, s_ar[t], iou, cost);
                if (!inb) cost += 1000000000.0f;
                if (cost < bestc) { bestc = cost; bestt = t; }   // first min = argmin
            }
            tp = bestt;
        }
        if (tp >= 0) {
            t_m = 1.f;
            float4 tb = s_tb[tp];
            float tx1 = tb.x, ty1 = tb.y, tx2 = tb.z, ty2 = tb.w;
            int ci = s_ci[tp];
            float ltx = fmaxf(pb.x, tx1), lty = fmaxf(pb.y, ty1);
            float rbx = fminf(pb.z, tx2), rby = fminf(pb.w, ty2);
            float wx = fmaxf(rbx - ltx, 0.f), wy = fmaxf(rby - lty, 0.f);
            float inter = wx * wy;
            float wp = pb.z - pb.x, hp = pb.w - pb.y;
            float wt = tx2 - tx1, ht = ty2 - ty1;
            float iou = inter / (wp*hp + wt*ht - inter + 1e-8f);
            float cw = fmaxf(pb.z, tx2) - fminf(pb.x, tx1);
            float chh = fmaxf(pb.w, ty2) - fminf(pb.y, ty1);
            float c2 = cw*cw + chh*chh + 1e-8f;
            float dx = pb.x + pb.z - (tx1 + tx2);
            float dy = pb.y + pb.w - (ty1 + ty2);
            float rho2 = (dx*dx + dy*dy) * 0.25f;
            const float k4pi2 = (float)(4.0 / (M_PI * M_PI));
            float dv = atanf(wt / (ht + 1e-8f)) - atanf(wp / (hp + 1e-8f));
            float v = k4pi2 * dv * dv;
            float alpha = v / (1.f - iou + v + 1e-8f);
            float ciou = iou - rho2 / c2 - alpha * v;
            t_lbox = 1.f - ciou;
            const float* prow = pred + (size_t)ba * 85;
            float s = 0.f;
            for (int c = 0; c < CC; c++)
                s += bce(prow[5 + c], (c == ci) ? 1.f : 0.f);
            t_lcls = s * (1.0f / CC);
        }
    }

    __shared__ float red[4*256];
    red[tid] = t_lbox; red[256 + tid] = t_m;
    red[512 + tid] = t_lobj; red[768 + tid] = t_lcls;
    __syncthreads();
    for (int s = 128; s > 0; s >>= 1) {
        if (tid < s) {
            red[tid]       += red[tid + s];
            red[256 + tid] += red[256 + tid + s];
            red[512 + tid] += red[512 + tid + s];
            red[768 + tid] += red[768 + tid + s];
        }
        __syncthreads();
    }
    if (tid == 0) {
        atomicAdd(&d_acc[0], (double)red[0]);
        atomicAdd(&d_acc[1], (double)red[256]);
        atomicAdd(&d_acc[2], (double)red[512]);
        atomicAdd(&d_acc[3], (double)red[768]);
        __threadfence();
        unsigned total = gridDim.x * gridDim.y;
        unsigned old = atomicAdd(&d_done, 1u);
        if (old == total - 1) {
            // last block: finalize (atomic reads ensure coherence), write out, reset
            double a0 = atomicAdd(&d_acc[0], 0.0);
            double a1 = atomicAdd(&d_acc[1], 0.0);
            double a2 = atomicAdd(&d_acc[2], 0.0);
            double a3 = atomicAdd(&d_acc[3], 0.0);
            double nm = a1 < 1.0 ? 1.0 : a1;
            float lbox = (float)(0.05 * a0 / nm);
            float lobj = (float)(a2 / (double)(NN));
            float lcls = (float)(0.5 * a3 / nm);
            float loss = lbox + lobj + lcls;
            if (out_n > 0) out[0] = loss;
            if (out_n > 1) out[1] = lbox;
            if (out_n > 2) out[2] = lobj;
            if (out_n > 3) out[3] = lcls;
            d_acc[0] = 0.0; d_acc[1] = 0.0; d_acc[2] = 0.0; d_acc[3] = 0.0;
            d_done = 0u;
        }
    }
}

// ---------------- launch ----------------
extern "C" void kernel_launch(void* const* d_in, const int* in_sizes, int n_in,
                              void* d_out, int out_size) {
    const float *pred = nullptr, *target = nullptr, *grid = nullptr, *stridem = nullptr;
    for (int i = 0; i < n_in; i++) {
        switch (in_sizes[i]) {
            case BB*AA*85:  pred    = (const float*)d_in[i]; break;
            case BB*TT*6:   target  = (const float*)d_in[i]; break;
            case AA*2:      grid    = (const float*)d_in[i]; break;
            case AA:        stridem = (const float*)d_in[i]; break;
            default: break;
        }
    }
    if (!pred    && n_in > 0) pred    = (const float*)d_in[0];
    if (!target  && n_in > 1) target  = (const float*)d_in[1];
    if (!grid    && n_in > 2) grid    = (const float*)d_in[2];
    if (!stridem && n_in > 3) stridem = (const float*)d_in[3];
    float* out = (float*)d_out;

    {
        dim3 g((AA + 255)/256, 4, BB);
        k_flags<<<g, 256>>>(target, grid, stridem);
    }
    {
        dim3 g((AA + 127)/128, BB);
        k_pass1<<<g, 512>>>(pred);
    }
    {
        dim3 g(32, BB);
        k_row<<<g, 256>>>(target, pred);
    }
    {
        dim3 g((AA + 255)/256, BB);
        k_col<<<g, 256>>>(pred, target, out, out_size);
    }
}

// round 17
// speedup vs baseline: 1.0587x; 1.0587x over previous
#include <cuda_runtime.h>
#include <math.h>
#include <float.h>
#include <limits.h>
#include <stdint.h>

#define BB 16
#define AA 8400
#define TT 128
#define CC 80
#define NN (BB*AA)
#define NG 4          // class groups in pass1
#define CG (CC/NG)    // classes per group (20)
#define NROWS (BB*TT)
#define CAP 128       // max stored ibc candidates per (b,t)
#define NGRP 263      // ceil(AA/32) anchor groups per image
#define NGRPH 132     // max groups per half

// ---------------- scratch (static device globals; no allocation) ----------------
// ALL state is either overwritten every launch or self-resetting (zero at launch
// entry; zero again at launch exit). CUDA zero-initializes these at module load.
__device__ float d_obj[NN];                     // obj logit (channel 4)
__device__ float d_A0[NN];                      // 1 + exp(-obj)
__device__ float2 d_SI[NN];                     // {S, in_box}
__device__ float d_apf[NN];                     // in_box ? area_p : -1e30
__device__ float4 d_pbox[NN];                   // pred boxes packed
__device__ float4 d_gbb[BB*NGRP];               // per-32-anchor-group bbox of in-box pred boxes
__device__ unsigned char d_inb[NN];             // in_box byte
__device__ unsigned char d_any4[(size_t)4*NN];  // per-chunk any flag
__device__ unsigned int d_ibc[BB*4*AA];         // in_box&in_center bitmask, word-major
__device__ float d_rowmax[NROWS];
__device__ int   d_mcnt[NN];                    // zero between launches
__device__ int   d_mt[NN];                      // holds max(TT - t); zero between launches
__device__ int   d_ccount[NROWS];               // zero between launches
__device__ int   d_clist[(size_t)NROWS*CAP];    // ibc candidate anchors per row
__device__ double d_acc[4];                     // zero between launches
__device__ unsigned int d_done;                 // zero between launches

__device__ __forceinline__ float bce(float x, float t) {
    return fmaxf(x, 0.f) - x * t + __logf(1.f + __expf(-fabsf(x)));
}
// jax.lax.top_k: stable — larger value first, ties -> smaller index first
__device__ __forceinline__ bool better(float k1, int i1, float k2, int i2) {
    return (k1 > k2) || (k1 == k2 && i1 < i2);
}

// D = logp - log1mp recomputed from A0 and class logit — one formula, all consumers
__device__ __forceinline__ float computeD(float A0, float x) {
    float u  = A0 * (1.f + __expf(-x));      // = 1/(so*sc)
    float p  = rsqrtf(u);
    float lp = fmaxf(-0.5f * __logf(u), -100.f);
    float l1 = fmaxf(__logf(1.f - p), -100.f);
    return lp - l1;
}

// register-resident indexed top-10 insert (static indexing, no spill)
__device__ __forceinline__ void insert10(float (&lk)[10], int (&li)[10], float k, int i) {
    if (!better(k, i, lk[9], li[9])) return;
    bool p[10];
    #pragma unroll
    for (int q = 0; q < 10; q++) p[q] = better(k, i, lk[q], li[q]);
    #pragma unroll
    for (int q = 9; q >= 1; q--) {
        if (p[q]) {
            lk[q] = p[q-1] ? lk[q-1] : k;
            li[q] = p[q-1] ? li[q-1] : i;
        }
    }
    if (p[0]) { lk[0] = k; li[0] = i; }
}

// branchless sorted top-10 VALUE network: 10 fmax + 10 fmin, no divergence
__device__ __forceinline__ void net10(float (&lk)[10], float v) {
    #pragma unroll
    for (int q = 0; q < 10; q++) {
        float hi = fmaxf(lk[q], v);
        v = fminf(lk[q], v);
        lk[q] = hi;
    }
}

// pair iou/cost for in-box anchors — identical math in row kernel and col conflict path
__device__ __forceinline__ void pair_iou_cost_inb(
    float4 pb, bool ibc, float S, float Dv,
    float x1, float y1, float x2, float y2, float area_t,
    float& iou_out, float& cost_out)
{
    float ltx = fmaxf(x1, pb.x), lty = fmaxf(y1, pb.y);
    float rbx = fminf(x2, pb.z), rby = fminf(y2, pb.w);
    float wx = fmaxf(rbx - ltx, 0.f), wy = fmaxf(rby - lty, 0.f);
    float inter = wx * wy;
    float area_p = fmaxf(pb.z - pb.x, 0.f) * fmaxf(pb.w - pb.y, 0.f);
    float iou = __fdividef(inter, area_t + area_p - inter + 1e-8f);
    float iouc = -__logf(iou + 1e-8f);
    float clsc = -(S + Dv);
    float cost = fmaf(3.0f, iouc, clsc);
    if (!ibc) cost += 100000.0f;
    iou_out = iou;
    cost_out = cost;
}

// ---------------- flags (runs FIRST): geometric flags + ibc candidate lists ----------------
__global__ void k_flags(const float* __restrict__ target,
                        const float* __restrict__ grid,
                        const float* __restrict__ str) {
    int b = blockIdx.z, ch = blockIdx.y;
    int a = blockIdx.x * blockDim.x + threadIdx.x;
    __shared__ float4 st4[32];
    __shared__ float2 sc2[32];
    if (threadIdx.x < 32) {
        const float* tb = target + ((size_t)b*TT + ch*32 + threadIdx.x)*6;
        float x1 = tb[2], y1 = tb[3], x2 = tb[4], y2 = tb[5];
        float4 v; v.x = x1; v.y = y1; v.z = x2; v.w = y2;
        st4[threadIdx.x] = v;
        float2 c; c.x = (x1 + x2) * 0.5f; c.y = (y1 + y2) * 0.5f;
        sc2[threadIdx.x] = c;
    }
    __syncthreads();
    if (a >= AA) return;
    float s = str[a];
    float xc = (grid[2*a] + 0.5f) * s;
    float yc = (grid[2*a+1] + 0.5f) * s;
    float r = 2.5f * s;
    unsigned w = 0;
    bool any = false;
    #pragma unroll 4
    for (int tt = 0; tt < 32; tt++) {
        float4 v = st4[tt];
        float2 c = sc2[tt];
        float dmin = fminf(fminf(xc - v.x, yc - v.y), fminf(v.z - xc, v.w - yc));
        bool ib = dmin > 0.f;
        bool ic = fmaxf(fabsf(xc - c.x), fabsf(yc - c.y)) < r;
        any |= (ib || ic);
        if (ib && ic) w |= (1u << tt);
    }
    d_ibc[(b*4 + ch)*AA + a] = w;
    d_any4[((size_t)ch*NN) + b*AA + a] = any ? 1 : 0;
    unsigned wb = w;
    while (wb) {
        int tt = __ffs(wb) - 1;
        wb &= wb - 1;
        int row = b*TT + ch*32 + tt;
        int p = atomicAdd(&d_ccount[row], 1);
        if (p < CAP) d_clist[(size_t)row*CAP + p] = a;
    }
}

// ---------------- pass1 (+combine fused): per-image blocks of 128 anchors ----------------
__global__ __launch_bounds__(512) void k_pass1(const float* __restrict__ pred) {
    __shared__ float tile[128*85];
    __shared__ float s_S[4][128];
    int b  = blockIdx.y;
    int a0 = blockIdx.x * 128;
    int cnt = min(128, AA - a0);
    const float* src = pred + ((size_t)b*AA + a0) * 85;
    for (int j = threadIdx.x; j < cnt*85; j += 512)
        tile[j] = src[j];
    __syncthreads();

    int al = threadIdx.x & 127;
    int g  = threadIdx.x >> 7;
    bool valid = al < cnt;
    int i  = b*AA + a0 + al;
    const float* row = tile + al*85;

    float S = 0.f;
    float4 pb = make_float4(0.f, 0.f, 0.f, 0.f);
    if (valid) {
        float xo = row[4];
        float A0 = 1.f + __expf(-xo);
        if (g == 0) {
            pb.x = row[0]; pb.y = row[1]; pb.z = row[2]; pb.w = row[3];
            d_pbox[i] = pb;
            d_obj[i] = xo;
            d_A0[i] = A0;
        }
        int c0 = g * CG;
        #pragma unroll 5
        for (int cc = 0; cc < CG; cc++) {
            float xc = row[5 + c0 + cc];
            float u  = A0 * (1.f + __expf(-xc));
            float p  = rsqrtf(u);
            float l1 = fmaxf(__logf(1.f - p), -100.f);
            S += l1;
        }
    }
    s_S[g][al] = S;
    __syncthreads();
    if (g != 0) return;

    bool inbv = false;
    if (valid) {
        float Ssum = s_S[0][al] + s_S[1][al] + s_S[2][al] + s_S[3][al];
        size_t ii = (size_t)i;
        unsigned char v = d_any4[ii] | d_any4[ii + (size_t)NN]
                        | d_any4[ii + (size_t)2*NN] | d_any4[ii + (size_t)3*NN];
        d_inb[i] = v;
        float2 si; si.x = Ssum; si.y = v ? 1.f : 0.f;
        d_SI[i] = si;
        float area_p = fmaxf(pb.z - pb.x, 0.f) * fmaxf(pb.w - pb.y, 0.f);
        d_apf[i] = v ? area_p : -1e30f;
        inbv = v != 0;
    }
    float bx1 = inbv ? pb.x :  FLT_MAX;
    float by1 = inbv ? pb.y :  FLT_MAX;
    float bx2 = inbv ? pb.z : -FLT_MAX;
    float by2 = inbv ? pb.w : -FLT_MAX;
    #pragma unroll
    for (int o = 16; o; o >>= 1) {
        bx1 = fminf(bx1, __shfl_xor_sync(0xffffffffu, bx1, o));
        by1 = fminf(by1, __shfl_xor_sync(0xffffffffu, by1, o));
        bx2 = fmaxf(bx2, __shfl_xor_sync(0xffffffffu, bx2, o));
        by2 = fmaxf(by2, __shfl_xor_sync(0xffffffffu, by2, o));
    }
    if ((al & 31) == 0 && valid) {
        float4 gg; gg.x = bx1; gg.y = by1; gg.z = bx2; gg.w = by2;
        d_gbb[b*NGRP + ((a0 + al) >> 5)] = gg;
    }
}

// ---------------- warp merges (smem scratch) ----------------
__device__ __forceinline__ void warp_merge10(float* K, int* I, int lane) {
    for (int step = 1; step < 32; step <<= 1) {
        __syncwarp();
        if ((lane & (2*step - 1)) == 0) {
            int o = lane*10, p = (lane + step)*10;
            int pa = 0, pb = 0;
            float ov[10]; int oi[10];
            #pragma unroll
            for (int j = 0; j < 10; j++) {
                float ka = K[o + pa]; int ia = I[o + pa];
                float kb = K[p + pb]; int ib = I[p + pb];
                if (better(ka, ia, kb, ib)) { ov[j] = ka; oi[j] = ia; pa++; }
                else                        { ov[j] = kb; oi[j] = ib; pb++; }
            }
            #pragma unroll
            for (int j = 0; j < 10; j++) { K[o + j] = ov[j]; I[o + j] = oi[j]; }
        }
    }
    __syncwarp();
}

__device__ __forceinline__ void warp_merge10v(float* K, int lane) {
    for (int step = 1; step < 32; step <<= 1) {
        __syncwarp();
        if ((lane & (2*step - 1)) == 0) {
            int o = lane*10, p = (lane + step)*10;
            int pa = 0, pb = 0;
            float ov[10];
            #pragma unroll
            for (int j = 0; j < 10; j++) {
                float ka = K[o + pa];
                float kb = K[p + pb];
                if (ka >= kb) { ov[j] = ka; pa++; }
                else          { ov[j] = kb; pb++; }
            }
            #pragma unroll
            for (int j = 0; j < 10; j++) K[o + j] = ov[j];
        }
    }
    __syncwarp();
}

// ---------------- row pass: 4 rows x 2 warps, ballot compaction, dual-list ILP scan ----------------
__global__ __launch_bounds__(256) void k_row(const float* __restrict__ target,
                                             const float* __restrict__ pred) {
    __shared__ __align__(16) float4 s_gb[NGRP];   // group bboxes, staged once
    __shared__ float mKs[8*320];
    __shared__ int   mIs[8*320];
    __shared__ int   s_list[8][NGRPH];            // per-warp surviving group ids

    int b  = blockIdx.y;
    int tg = blockIdx.x;                     // 0..31 target groups of 4
    int warp = threadIdx.x >> 5, lane = threadIdx.x & 31;
    int t = tg*4 + (warp >> 1);
    int half = warp & 1;
    int row = b*TT + t;
    const float* tr = target + (size_t)row * 6;
    float x1 = tr[2], y1 = tr[3], x2 = tr[4], y2 = tr[5];
    int ci = (int)tr[1];
    float area_t = fmaxf(x2 - x1, 0.f) * fmaxf(y2 - y1, 0.f);
    float area_te = area_t + 1e-8f;
    unsigned tbit = 1u << (t & 31);
    int chunk = t >> 5;

    const float4* Pg = d_pbox + b*AA;
    const float*  Ag = d_apf + b*AA;
    const float2* Sg = d_SI + b*AA;
    const unsigned* Wg = d_ibc + (b*4 + chunk)*AA;

    for (int g = threadIdx.x; g < NGRP; g += 256)
        s_gb[g] = d_gbb[b*NGRP + g];
    __syncthreads();

    // ---- ballot compaction: each lane tests a different group ----
    int nHalf = (NGRP - half + 1) >> 1;
    int cntw = 0;
    #pragma unroll
    for (int r = 0; r < (NGRPH + 31)/32; r++) {
        int j = lane + r*32;
        int g = half + 2*j;
        bool surv = false;
        if (j < nHalf) {
            float4 gb = s_gb[g];
            surv = !(gb.x >= x2 || gb.z <= x1 || gb.y >= y2 || gb.w <= y1);
        }
        unsigned m = __ballot_sync(0xffffffffu, surv);
        if (surv) s_list[warp][cntw + __popc(m & ((1u << lane) - 1))] = g;
        cntw += __popc(m);
    }

    // ---- dual-list scan: 2 groups/iter into independent top-10 lists ----
    float lkA[10], lkB[10];
    #pragma unroll
    for (int j = 0; j < 10; j++) { lkA[j] = 0.f; lkB[j] = 0.f; }

    int k = 0;
    for (; k + 1 < cntw; k += 2) {
        int g0 = s_list[warp][k], g1 = s_list[warp][k+1];
        int a0 = g0*32 + lane,    a1 = g1*32 + lane;
        bool v0 = a0 < AA, v1 = a1 < AA;
        float4 p0, p1; float q0, q1;
        if (v0) { p0 = Pg[a0]; q0 = Ag[a0]; }
        if (v1) { p1 = Pg[a1]; q1 = Ag[a1]; }
        if (v0) {
            float ltx = fmaxf(x1, p0.x), lty = fmaxf(y1, p0.y);
            float rbx = fminf(x2, p0.z), rby = fminf(y2, p0.w);
            float wx = fmaxf(rbx - ltx, 0.f), wy = fmaxf(rby - lty, 0.f);
            float inter = wx * wy;
            float iou = __fdividef(inter, (area_te + q0) - inter);
            net10(lkA, iou);
        }
        if (v1) {
            float ltx = fmaxf(x1, p1.x), lty = fmaxf(y1, p1.y);
            float rbx = fminf(x2, p1.z), rby = fminf(y2, p1.w);
            float wx = fmaxf(rbx - ltx, 0.f), wy = fmaxf(rby - lty, 0.f);
            float inter = wx * wy;
            float iou = __fdividef(inter, (area_te + q1) - inter);
            net10(lkB, iou);
        }
    }
    if (k < cntw) {
        int g0 = s_list[warp][k];
        int a0 = g0*32 + lane;
        if (a0 < AA) {
            float4 p0 = Pg[a0]; float q0 = Ag[a0];
            float ltx = fmaxf(x1, p0.x), lty = fmaxf(y1, p0.y);
            float rbx = fminf(x2, p0.z), rby = fminf(y2, p0.w);
            float wx = fmaxf(rbx - ltx, 0.f), wy = fmaxf(rby - lty, 0.f);
            float inter = wx * wy;
            float iou = __fdividef(inter, (area_te + q0) - inter);
            net10(lkA, iou);
        }
    }
    #pragma unroll
    for (int j = 0; j < 10; j++) net10(lkA, lkB[j]);

    float* mK = mKs + warp*320;
    int*   mI = mIs + warp*320;

    #pragma unroll
    for (int j = 0; j < 10; j++) mK[lane*10 + j] = lkA[j];
    warp_merge10v(mK, lane);
    __syncthreads();

    if (half == 1) return;

    int dk = 0;
    if (lane == 0) {
        float* pK = mKs + (warp + 1)*320;
        float ov[10];
        int pa = 0, pb = 0;
        #pragma unroll
        for (int j = 0; j < 10; j++) {
            float ka = mK[pa], kb = pK[pb];
            if (ka >= kb) { ov[j] = ka; pa++; }
            else          { ov[j] = kb; pb++; }
        }
        float s = 0.f;
        #pragma unroll
        for (int j = 0; j < 10; j++) s += ov[j];
        dk = (int)s;
        if (dk < 1) dk = 1; if (dk > 10) dk = 10;
        d_rowmax[row] = ov[0];
    }
    dk = __shfl_sync(0xffffffffu, dk, 0);
    __syncwarp();

    // ---- cost phase (even warp only): ibc candidate list ----
    float lkC[10]; int liC[10];
    #pragma unroll
    for (int j = 0; j < 10; j++) { lkC[j] = -FLT_MAX; liC[j] = INT_MAX; }
    int cnt = d_ccount[row];
    if (cnt >= 10 && cnt <= CAP) {
        const int* lst = d_clist + (size_t)row*CAP;
        for (int kk = lane; kk < cnt; kk += 32) {
            int a = lst[kk];
            float4 pb = Pg[a];
            float S = Sg[a].x;
            float Dv = computeD(d_A0[b*AA + a],
                                pred[((size_t)(b*AA + a))*85 + 5 + ci]);
            float iou, cost;
            pair_iou_cost_inb(pb, true, S, Dv, x1, y1, x2, y2, area_t, iou, cost);
            insert10(lkC, liC, -cost, a);
        }
    } else {
        for (int a = lane; a < AA; a += 32) {
            float4 pb = Pg[a];
            float2 si = Sg[a];
            bool inb = si.y != 0.f;
            bool ibc = (Wg[a] & tbit) != 0;
            float Dv = computeD(d_A0[b*AA + a],
                                pred[((size_t)(b*AA + a))*85 + 5 + ci]);
            float iou, cost;
            pair_iou_cost_inb(pb, ibc, si.x, Dv, x1, y1, x2, y2, area_t, iou, cost);
            if (!inb) cost += 1000000000.0f;
            insert10(lkC, liC, -cost, a);
        }
    }

    #pragma unroll
    for (int j = 0; j < 10; j++) { mK[lane*10 + j] = lkC[j]; mI[lane*10 + j] = liC[j]; }
    warp_merge10(mK, mI, lane);
    if (lane == 0) {
        for (int j = 0; j < dk; j++) {
            int aa = mI[j];
            if (aa == INT_MAX) break;
            if (d_inb[b*AA + aa]) {
                atomicAdd(&d_mcnt[b*AA + aa], 1);
                atomicMax(&d_mt[b*AA + aa], TT - t);   // max(TT-t) == min t; zero-init safe
            }
        }
        d_ccount[row] = 0;   // self-reset for next launch
    }
}

// ---------------- col pass (+finalize): target-compacted piou + conflict argmin + loss ----------------
__global__ __launch_bounds__(256) void k_col(const float* __restrict__ pred,
                                             const float* __restrict__ target,
                                             float* __restrict__ out, int out_n) {
    int b = blockIdx.y;
    int a = blockIdx.x * blockDim.x + threadIdx.x;
    int tid = threadIdx.x;
    int warp = tid >> 5, lane = tid & 31;
    __shared__ float4 s_tb[TT];
    __shared__ float s_ar[TT], s_inv[TT];
    __shared__ int   s_ci[TT];
    __shared__ int   s_tl[8][TT];          // per-warp surviving target ids
    if (tid < TT) {
        const float* tb = target + ((size_t)b*TT + tid)*6;
        float X1 = tb[2], Y1 = tb[3], X2 = tb[4], Y2 = tb[5];
        float4 v; v.x = X1; v.y = Y1; v.z = X2; v.w = Y2;
        s_tb[tid] = v;
        s_ar[tid] = fmaxf(X2 - X1, 0.f) * fmaxf(Y2 - Y1, 0.f);
        s_ci[tid] = (int)tb[1];
        s_inv[tid] = __fdividef(1.f, d_rowmax[b*TT + tid] + 1e-8f);
    }
    __syncthreads();

    // ---- warp-group target compaction (warp-uniform bbox test) ----
    int grp = blockIdx.x*8 + warp;         // this warp's 32-anchor group
    float4 gb;
    if (grp < NGRP) gb = d_gbb[b*NGRP + grp];
    else { gb.x = FLT_MAX; gb.y = FLT_MAX; gb.z = -FLT_MAX; gb.w = -FLT_MAX; }
    int ntl = 0;
    #pragma unroll
    for (int r = 0; r < TT/32; r++) {
        int t = lane + r*32;
        float4 tb = s_tb[t];
        // skip exact: group bbox disjoint from target -> inter==0 for all inb anchors
        bool surv = !(gb.x >= tb.z || gb.z <= tb.x || gb.y >= tb.w || gb.w <= tb.y);
        unsigned m = __ballot_sync(0xffffffffu, surv);
        if (surv) s_tl[warp][ntl + __popc(m & ((1u << lane) - 1))] = t;
        ntl += __popc(m);
    }

    float t_lbox = 0.f, t_m = 0.f, t_lobj = 0.f, t_lcls = 0.f;
    if (a < AA) {
        int ba = b*AA + a;
        float4 pb = d_pbox[ba];
        float2 si = d_SI[ba];
        bool inb = si.y != 0.f;
        float S = si.x;

        // piou over surviving targets only (skipped contribute exactly 0)
        float area_p = fmaxf(pb.z - pb.x, 0.f) * fmaxf(pb.w - pb.y, 0.f);
        float piou0 = 0.f, piou1 = 0.f;
        int kk = 0;
        for (; kk + 1 < ntl; kk += 2) {
            int t0 = s_tl[warp][kk], t1 = s_tl[warp][kk+1];
            float4 tb0 = s_tb[t0], tb1 = s_tb[t1];
            {
                float ltx = fmaxf(tb0.x, pb.x), lty = fmaxf(tb0.y, pb.y);
                float rbx = fminf(tb0.z, pb.z), rby = fminf(tb0.w, pb.w);
                float wx = fmaxf(rbx - ltx, 0.f), wy = fmaxf(rby - lty, 0.f);
                float inter = wx * wy;
                float iou = __fdividef(inter, s_ar[t0] + area_p - inter + 1e-8f);
                piou0 = fmaxf(piou0, iou * s_inv[t0]);
            }
            {
                float ltx = fmaxf(tb1.x, pb.x), lty = fmaxf(tb1.y, pb.y);
                float rbx = fminf(tb1.z, pb.z), rby = fminf(tb1.w, pb.w);
                float wx = fmaxf(rbx - ltx, 0.f), wy = fmaxf(rby - lty, 0.f);
                float inter = wx * wy;
                float iou = __fdividef(inter, s_ar[t1] + area_p - inter + 1e-8f);
                piou1 = fmaxf(piou1, iou * s_inv[t1]);
            }
        }
        if (kk < ntl) {
            int t0 = s_tl[warp][kk];
            float4 tb0 = s_tb[t0];
            float ltx = fmaxf(tb0.x, pb.x), lty = fmaxf(tb0.y, pb.y);
            float rbx = fminf(tb0.z, pb.z), rby = fminf(tb0.w, pb.w);
            float wx = fmaxf(rbx - ltx, 0.f), wy = fmaxf(rby - lty, 0.f);
            float inter = wx * wy;
            float iou = __fdividef(inter, s_ar[t0] + area_p - inter + 1e-8f);
            piou0 = fmaxf(piou0, iou * s_inv[t0]);
        }
        float piou = fmaxf(piou0, piou1);   // max associative: exact

        float objt = inb ? fminf(fmaxf(piou, 0.f), 1.f) : 0.f;
        t_lobj = bce(d_obj[ba], objt);

        int cnt = d_mcnt[ba];
        int mtv = d_mt[ba];
        if (cnt != 0) { d_mcnt[ba] = 0; d_mt[ba] = 0; }   // self-reset
        int tp = -1;
        if (cnt == 1) tp = TT - mtv;
        else if (cnt > 1) {
            unsigned wv[4];
            #pragma unroll
            for (int ch = 0; ch < 4; ch++) wv[ch] = d_ibc[(b*4 + ch)*AA + a];
            const float* prow = pred + (size_t)ba * 85;
            float A0 = d_A0[ba];
            float bestc = FLT_MAX; int bestt = 0;
            for (int t = 0; t < TT; t++) {
                bool ibc = (wv[t >> 5] >> (t & 31)) & 1u;
                float4 tb = s_tb[t];
                float Dv = computeD(A0, prow[5 + s_ci[t]]);
                float iou, cost;
                pair_iou_cost_inb(pb, ibc, S, Dv,
                                  tb.x, tb.y, tb.z, tb.w, s_ar[t], iou, cost);
                if (!inb) cost += 1000000000.0f;
                if (cost < bestc) { bestc = cost; bestt = t; }   // first min = argmin
            }
            tp = bestt;
        }
        if (tp >= 0) {
            t_m = 1.f;
            float4 tb = s_tb[tp];
            float tx1 = tb.x, ty1 = tb.y, tx2 = tb.z, ty2 = tb.w;
            int ci = s_ci[tp];
            float ltx = fmaxf(pb.x, tx1), lty = fmaxf(pb.y, ty1);
            float rbx = fminf(pb.z, tx2), rby = fminf(pb.w, ty2);
            float wx = fmaxf(rbx - ltx, 0.f), wy = fmaxf(rby - lty, 0.f);
            float inter = wx * wy;
            float wp = pb.z - pb.x, hp = pb.w - pb.y;
            float wt = tx2 - tx1, ht = ty2 - ty1;
            float iou = inter / (wp*hp + wt*ht - inter + 1e-8f);
            float cw = fmaxf(pb.z, tx2) - fminf(pb.x, tx1);
            float chh = fmaxf(pb.w, ty2) - fminf(pb.y, ty1);
            float c2 = cw*cw + chh*chh + 1e-8f;
            float dx = pb.x + pb.z - (tx1 + tx2);
            float dy = pb.y + pb.w - (ty1 + ty2);
            float rho2 = (dx*dx + dy*dy) * 0.25f;
            const float k4pi2 = (float)(4.0 / (M_PI * M_PI));
            float dv = atanf(wt / (ht + 1e-8f)) - atanf(wp / (hp + 1e-8f));
            float v = k4pi2 * dv * dv;
            float alpha = v / (1.f - iou + v + 1e-8f);
            float ciou = iou - rho2 / c2 - alpha * v;
            t_lbox = 1.f - ciou;
            const float* prow = pred + (size_t)ba * 85;
            float s = 0.f;
            for (int c = 0; c < CC; c++)
                s += bce(prow[5 + c], (c == ci) ? 1.f : 0.f);
            t_lcls = s * (1.0f / CC);
        }
    }

    __shared__ float red[4*256];
    red[tid] = t_lbox; red[256 + tid] = t_m;
    red[512 + tid] = t_lobj; red[768 + tid] = t_lcls;
    __syncthreads();
    for (int s = 128; s > 0; s >>= 1) {
        if (tid < s) {
            red[tid]       += red[tid + s];
            red[256 + tid] += red[256 + tid + s];
            red[512 + tid] += red[512 + tid + s];
            red[768 + tid] += red[768 + tid + s];
        }
        __syncthreads();
    }
    if (tid == 0) {
        atomicAdd(&d_acc[0], (double)red[0]);
        atomicAdd(&d_acc[1], (double)red[256]);
        atomicAdd(&d_acc[2], (double)red[512]);
        atomicAdd(&d_acc[3], (double)red[768]);
        __threadfence();
        unsigned total = gridDim.x * gridDim.y;
        unsigned old = atomicAdd(&d_done, 1u);
        if (old == total - 1) {
            double a0 = atomicAdd(&d_acc[0], 0.0);
            double a1 = atomicAdd(&d_acc[1], 0.0);
            double a2 = atomicAdd(&d_acc[2], 0.0);
            double a3 = atomicAdd(&d_acc[3], 0.0);
            double nm = a1 < 1.0 ? 1.0 : a1;
            float lbox = (float)(0.05 * a0 / nm);
            float lobj = (float)(a2 / (double)(NN));
            float lcls = (float)(0.5 * a3 / nm);
            float loss = lbox + lobj + lcls;
            if (out_n > 0) out[0] = loss;
            if (out_n > 1) out[1] = lbox;
            if (out_n > 2) out[2] = lobj;
            if (out_n > 3) out[3] = lcls;
            d_acc[0] = 0.0; d_acc[1] = 0.0; d_acc[2] = 0.0; d_acc[3] = 0.0;
            d_done = 0u;
        }
    }
}

// ---------------- launch ----------------
extern "C" void kernel_launch(void* const* d_in, const int* in_sizes, int n_in,
                              void* d_out, int out_size) {
    const float *pred = nullptr, *target = nullptr, *grid = nullptr, *stridem = nullptr;
    for (int i = 0; i < n_in; i++) {
        switch (in_sizes[i]) {
            case BB*AA*85:  pred    = (const float*)d_in[i]; break;
            case BB*TT*6:   target  = (const float*)d_in[i]; break;
            case AA*2:      grid    = (const float*)d_in[i]; break;
            case AA:        stridem = (const float*)d_in[i]; break;
            default: break;
        }
    }
    if (!pred    && n_in > 0) pred    = (const float*)d_in[0];
    if (!target  && n_in > 1) target  = (const float*)d_in[1];
    if (!grid    && n_in > 2) grid    = (const float*)d_in[2];
    if (!stridem && n_in > 3) stridem = (const float*)d_in[3];
    float* out = (float*)d_out;

    {
        dim3 g((AA + 255)/256, 4, BB);
        k_flags<<<g, 256>>>(target, grid, stridem);
    }
    {
        dim3 g((AA + 127)/128, BB);
        k_pass1<<<g, 512>>>(pred);
    }
    {
        dim3 g(32, BB);
        k_row<<<g, 256>>>(target, pred);
    }
    {
        dim3 g((AA + 255)/256, BB);
        k_col<<<g, 256>>>(pred, target, out, out_size);
    }
}